// round 16
// baseline (speedup 1.0000x reference)
#include <cuda_runtime.h>
#include <cuda_fp16.h>
#include <cstdint>

// ComplexBlockLinear, mma.sync fp16 m16n8k16. Round 16:
//  - X converted to f16 ONCE at staging (LDG f32 + pack + STS f16), A frags
//    via ldmatrix.x4 from XOR-swizzled f16 smem. Conversion dedupe 4x,
//    A-side smem bytes halve.
//  - LDG for chunk c+1 issued under compute of c (regs), STS at top of c+1.
//  - W path identical to R14: planar f16 planes + cp.async + x4.trans.
// CTA = 64 rows x 1 block, 8 warps (2M x 4N), warp tile 32x32, KC=32,
// 256 thr, 2 CTAs/SM.

#define NBLK 8
#define BS 128
#define HD 1024
#define CTA_M 64
#define KC 32
#define NCHUNK (BS / KC)     // 4
#define THREADS 256

// per-stage smem:
//   X  : f16, both arrays, swizzled granules                     8192 B
//   WR/WI: 32 k-rows x 272 B (128 f16 + 8 pad)                   8704 B each
#define X_OFF  0
#define WR_OFF 8192
#define WI_OFF 16896
#define STAGE_BYTES 25600
#define SMEM_TOTAL (2 * STAGE_BYTES)   // 51200
#define WROWB 272

// pre-converted weight planes, [nblk*128 k][128 n] f16
__device__ __align__(16) __half g_wre[NBLK * BS * BS];
__device__ __align__(16) __half g_wim[NBLK * BS * BS];

__device__ __forceinline__ uint32_t smem_u32(const void* p) {
    uint32_t a;
    asm("{ .reg .u64 t; cvta.to.shared.u64 t, %1; cvt.u32.u64 %0, t; }"
        : "=r"(a) : "l"(p));
    return a;
}
__device__ __forceinline__ unsigned pack_h2(float lo, float hi) {
    unsigned d;
    asm("cvt.rn.f16x2.f32 %0, %1, %2;" : "=r"(d) : "f"(hi), "f"(lo));
    return d;
}
__device__ __forceinline__ void cp16(uint32_t dst, const void* src) {
    asm volatile("cp.async.ca.shared.global [%0], [%1], 16;"
                 :: "r"(dst), "l"(src) : "memory");
}
__device__ __forceinline__ void cp_commit() {
    asm volatile("cp.async.commit_group;" ::: "memory");
}
template <int N>
__device__ __forceinline__ void cp_wait() {
    asm volatile("cp.async.wait_group %0;" :: "n"(N) : "memory");
}
__device__ __forceinline__ void sts128(uint32_t addr, unsigned a, unsigned b,
                                       unsigned c, unsigned d) {
    asm volatile("st.shared.v4.b32 [%0], {%1,%2,%3,%4};"
                 :: "r"(addr), "r"(a), "r"(b), "r"(c), "r"(d) : "memory");
}
// non-trans x4: reg j = 8x8 matrix addressed by lanes 8j..8j+7
__device__ __forceinline__ void ldsm_x4(unsigned& r0, unsigned& r1,
                                        unsigned& r2, unsigned& r3,
                                        uint32_t addr) {
    asm volatile(
        "ldmatrix.sync.aligned.m8n8.x4.shared.b16 {%0,%1,%2,%3},[%4];"
        : "=r"(r0), "=r"(r1), "=r"(r2), "=r"(r3) : "r"(addr));
}
__device__ __forceinline__ void ldsm_x4t(unsigned& r0, unsigned& r1,
                                         unsigned& r2, unsigned& r3,
                                         uint32_t addr) {
    asm volatile(
        "ldmatrix.sync.aligned.m8n8.x4.trans.shared.b16 {%0,%1,%2,%3},[%4];"
        : "=r"(r0), "=r"(r1), "=r"(r2), "=r"(r3) : "r"(addr));
}
__device__ __forceinline__ void mma_f16(float* d, const unsigned* a,
                                        unsigned b0, unsigned b1) {
    asm volatile(
        "mma.sync.aligned.m16n8k16.row.col.f32.f16.f16.f32 "
        "{%0,%1,%2,%3},{%4,%5,%6,%7},{%8,%9},{%0,%1,%2,%3};\n"
        : "+f"(d[0]), "+f"(d[1]), "+f"(d[2]), "+f"(d[3])
        : "r"(a[0]), "r"(a[1]), "r"(a[2]), "r"(a[3]), "r"(b0), "r"(b1));
}

// ---- weight conversion: [8,128,128,2] f32 -> planar f16 ----
__global__ void wconv_kernel(const float* __restrict__ w) {
    const int idx = blockIdx.x * 256 + threadIdx.x;   // 0..131071
    const float2 v = ((const float2*)w)[idx];
    g_wre[idx] = __float2half_rn(v.x);
    g_wim[idx] = __float2half_rn(v.y);
}

__global__ __launch_bounds__(THREADS, 2)
void cbl_h16q_kernel(const float* __restrict__ xre,
                     const float* __restrict__ xim,
                     float* __restrict__ out) {
    extern __shared__ char smem[];
    const uint32_t sb = smem_u32(smem);

    const int tid  = threadIdx.x;
    const int lane = tid & 31;
    const int warp = tid >> 5;
    const int wm   = warp >> 2;    // 0..1
    const int wn   = warp & 3;     // 0..3

    const int row0 = blockIdx.x * CTA_M;
    const int nb   = blockIdx.y;

    float accR[2][4][4], accI[2][4][4];
#pragma unroll
    for (int a = 0; a < 2; a++)
#pragma unroll
        for (int b = 0; b < 4; b++)
#pragma unroll
            for (int c = 0; c < 4; c++) { accR[a][b][c] = 0.f; accI[a][b][c] = 0.f; }

    // ---- X staging thread mapping: (arr, row, s-half)
    const int st_arr = tid >> 7;          // 0: re, 1: im
    const int st_rem = tid & 127;
    const int st_row = st_rem >> 1;       // 0..63
    const int st_s   = st_rem & 1;        // k16 half
    const float* xsrc = (st_arr ? xim : xre) +
        (size_t)(row0 + st_row) * HD + nb * BS + st_s * 16;
    // swizzled granule slots for this thread's two STS
    const uint32_t st_blk = (uint32_t)(st_s * 64 + st_row) * 64;
    const uint32_t st_gp0 =
        (uint32_t)(((st_arr << 1) ^ ((st_row >> 1) & 3) ^ (st_s << 1)) * 16);

    unsigned h[8];   // staged f16x2 for next chunk (held across compute)

    auto ldgx = [&](int c) {
        const float4* p = (const float4*)(xsrc + c * KC);
        const float4 v0 = p[0], v1 = p[1], v2 = p[2], v3 = p[3];
        h[0] = pack_h2(v0.x, v0.y); h[1] = pack_h2(v0.z, v0.w);
        h[2] = pack_h2(v1.x, v1.y); h[3] = pack_h2(v1.z, v1.w);
        h[4] = pack_h2(v2.x, v2.y); h[5] = pack_h2(v2.z, v2.w);
        h[6] = pack_h2(v3.x, v3.y); h[7] = pack_h2(v3.z, v3.w);
    };
    auto stsx = [&](int c) {
        const uint32_t xb = sb + (c & 1) * STAGE_BYTES + X_OFF;
        const uint32_t a0 = xb + st_blk + st_gp0;
        sts128(a0,      h[0], h[1], h[2], h[3]);   // khalf0
        sts128(a0 ^ 16, h[4], h[5], h[6], h[7]);   // khalf1 (g' ^= 1)
    };
    auto cpw = [&](int c) {
        const uint32_t base = sb + (c & 1) * STAGE_BYTES;
        const int k0 = c * KC;
#pragma unroll
        for (int q = 0; q < 4; ++q) {
            const int e   = q * THREADS + tid;     // 0..1023
            const int arr = e >> 9;
            const int kk  = (e >> 4) & 31;
            const int c16 = e & 15;
            const __half* src = (arr ? g_wim : g_wre) +
                (size_t)(nb * BS + k0 + kk) * BS + c16 * 8;
            cp16(base + (arr ? WI_OFF : WR_OFF) + kk * WROWB + c16 * 16, src);
        }
        cp_commit();
    };

    // A-frag ldmatrix lane constants
    const int j      = lane >> 3;
    const int lrow   = lane & 7;
    const int rowoff = (j & 1) * 8 + lrow;
    const int khalf  = j >> 1;
    const uint32_t A_l = (uint32_t)rowoff * 64;
    const int Gl = khalf ^ ((rowoff >> 1) & 3);

    // B ldmatrix lane base: lanes 0-15 -> WR, 16-31 -> WI
    const uint32_t ldsm_kr   = (uint32_t)((lane & 7) + ((lane >> 3) & 1) * 8);
    const uint32_t ldsm_base = ((lane & 16) ? WI_OFF : WR_OFF) + ldsm_kr * WROWB;

    // prologue
    ldgx(0);
    cpw(0);

#pragma unroll 1
    for (int c = 0; c < NCHUNK; ++c) {
        stsx(c);               // buffer c&1 free (readers retired 2 iters ago)
        cp_wait<0>();          // W(c) complete
        __syncthreads();       // publish X(c) f16 + W(c)
        if (c + 1 < NCHUNK) { cpw(c + 1); ldgx(c + 1); }

        const uint32_t base = sb + (c & 1) * STAGE_BYTES;
        const uint32_t xb   = base + X_OFF;

#pragma unroll
        for (int s = 0; s < 2; ++s) {     // two k16 steps per chunk
            // ---- A fragments: one ldmatrix.x4 per (mt, arr)
            unsigned ar[2][4], ai[2][4];
            const uint32_t sgp = (uint32_t)((Gl ^ (s << 1)) * 16);
#pragma unroll
            for (int mt = 0; mt < 2; ++mt) {
                const uint32_t aadr = xb +
                    (uint32_t)(s * 4096 + wm * 2048 + mt * 1024) + A_l + sgp;
                ldsm_x4(ar[mt][0], ar[mt][1], ar[mt][2], ar[mt][3], aadr);
                ldsm_x4(ai[mt][0], ai[mt][1], ai[mt][2], ai[mt][3],
                        aadr ^ 32);   // arr=1: g' ^= 2
            }

            // ---- B fragments: one ldmatrix.x4.trans per n-tile (re+im)
            const uint32_t krow = base + ldsm_base + (uint32_t)(s * 16) * WROWB;
#pragma unroll
            for (int nt = 0; nt < 4; ++nt) {
                const uint32_t ncol = (uint32_t)(wn * 32 + nt * 8) * 2;
                unsigned bR0, bR1, bI0, bI1;
                ldsm_x4t(bR0, bR1, bI0, bI1, krow + ncol);
                const unsigned nI0 = bI0 ^ 0x80008000u;
                const unsigned nI1 = bI1 ^ 0x80008000u;
#pragma unroll
                for (int mt = 0; mt < 2; ++mt) {
                    mma_f16(accR[mt][nt], ar[mt], bR0, bR1);
                    mma_f16(accR[mt][nt], ai[mt], nI0, nI1);
                    mma_f16(accI[mt][nt], ar[mt], bI0, bI1);
                    mma_f16(accI[mt][nt], ai[mt], bR0, bR1);
                }
            }
        }
        __syncthreads();   // retire buffer c&1 readers
    }

    // ---- epilogue: interleave (re,im) -> float4 stores, view_as_real layout
#pragma unroll
    for (int mt = 0; mt < 2; ++mt) {
        const int r_lo = row0 + wm * 32 + mt * 16 + (lane >> 2);
#pragma unroll
        for (int nt = 0; nt < 4; ++nt) {
            const int col = nb * BS + wn * 32 + nt * 8 + (lane & 3) * 2;
            float4 v0 = make_float4(accR[mt][nt][0], accI[mt][nt][0],
                                    accR[mt][nt][1], accI[mt][nt][1]);
            float4 v1 = make_float4(accR[mt][nt][2], accI[mt][nt][2],
                                    accR[mt][nt][3], accI[mt][nt][3]);
            *(float4*)(out + ((size_t)r_lo * HD + col) * 2)       = v0;
            *(float4*)(out + ((size_t)(r_lo + 8) * HD + col) * 2) = v1;
        }
    }
}

extern "C" void kernel_launch(void* const* d_in, const int* in_sizes, int n_in,
                              void* d_out, int out_size) {
    const float* xre = (const float*)d_in[0];
    const float* xim = (const float*)d_in[1];
    const float* w   = (const float*)d_in[2];
    float* out       = (float*)d_out;

    wconv_kernel<<<NBLK * BS * BS / 256, 256>>>(w);

    cudaFuncSetAttribute(cbl_h16q_kernel,
                         cudaFuncAttributeMaxDynamicSharedMemorySize, SMEM_TOTAL);
    dim3 grid(32768 / CTA_M, NBLK);   // (512, 8)
    cbl_h16q_kernel<<<grid, THREADS, SMEM_TOTAL>>>(xre, xim, out);
}